// round 4
// baseline (speedup 1.0000x reference)
#include <cuda_runtime.h>
#include <math.h>

// Problem dims
#define NB 2048
#define NT 512
#define NP 8
#define NL 64
#define NH 180
#define NH3 540
#define KIN (NP+NL)     // 72
#define KO1 (NH+NL)     // 244

#define RT 16           // batch rows per CTA
#define NCTA (NB/RT)    // 128
#define THREADS 256

typedef unsigned long long u64;

// -------- K-major (transposed) weights, padded by 4 k-rows for prefetch ----
__device__ float g_WTin[(KIN+4)*NH];
__device__ float g_WThp[(NL+4)*NH];
__device__ float g_WTih[(NH+4)*NH3];
__device__ float g_WThh[(NH+4)*NH3];
__device__ float g_WTo1[(KO1+4)*NH];
__device__ float g_WTo2[(NH+4)*NL];

// grid barrier state
__device__ unsigned g_cnt = 0;
__device__ volatile unsigned g_rel = 0;

__device__ __forceinline__ u64 ff2(u64 a, u64 b, u64 c) {
    u64 d;
    asm("fma.rn.f32x2 %0, %1, %2, %3;" : "=l"(d) : "l"(a), "l"(b), "l"(c));
    return d;
}
__device__ __forceinline__ u64 dup2(float w) {
    u64 d;
    asm("mov.b64 %0, {%1, %1};" : "=l"(d) : "f"(w), "f"(w));
    return d;
}
__device__ __forceinline__ void unpk(u64 p, float& lo, float& hi) {
    asm("mov.b64 {%0, %1}, %2;" : "=f"(lo), "=f"(hi) : "l"(p));
}
__device__ __forceinline__ void fq(const float* p, u64& a, u64& b) {
    double2 q = *reinterpret_cast<const double2*>(p);
    a = __double_as_longlong(q.x);
    b = __double_as_longlong(q.y);
}
__device__ __forceinline__ float gelu_f(float x) {
    return 0.5f * x * (1.0f + erff(x * 0.7071067811865476f));
}
__device__ __forceinline__ float sigmoid_f(float x) {
    return 1.0f / (1.0f + expf(-x));
}

// acc[rp][j] += A_pairs * W[:,c[j]] over k in [k0,k1). A is k-major, STRIDE floats/row.
template<int O, int STRIDE, int NC>
__device__ __forceinline__ void gemm2(const float* __restrict__ sAT,
                                      const float* __restrict__ W,
                                      const int* c, int k0, int k1,
                                      u64 (&acc)[8][NC])
{
#pragma unroll
    for (int rp = 0; rp < 8; rp++)
#pragma unroll
        for (int j = 0; j < NC; j++) acc[rp][j] = 0ull;

    float w[4][NC];
#pragma unroll
    for (int kk = 0; kk < 4; kk++)
#pragma unroll
        for (int j = 0; j < NC; j++) w[kk][j] = W[(k0 + kk) * O + c[j]];

#pragma unroll 1
    for (int k = k0; k < k1; k += 4) {
        float wn[4][NC];
#pragma unroll
        for (int kk = 0; kk < 4; kk++)
#pragma unroll
            for (int j = 0; j < NC; j++) wn[kk][j] = W[(k + 4 + kk) * O + c[j]];
#pragma unroll
        for (int kk = 0; kk < 4; kk++) {
            u64 a[8];
            const float* ap = sAT + (k + kk) * STRIDE;
            fq(ap + 0,  a[0], a[1]);
            fq(ap + 4,  a[2], a[3]);
            fq(ap + 8,  a[4], a[5]);
            fq(ap + 12, a[6], a[7]);
#pragma unroll
            for (int j = 0; j < NC; j++) {
                u64 wp = dup2(w[kk][j]);
#pragma unroll
                for (int rp = 0; rp < 8; rp++)
                    acc[rp][j] = ff2(a[rp], wp, acc[rp][j]);
            }
        }
#pragma unroll
        for (int kk = 0; kk < 4; kk++)
#pragma unroll
            for (int j = 0; j < NC; j++) w[kk][j] = wn[kk][j];
    }
}

// SMEM layout (floats)
#define OFF_INT  0                     // sInT [72][20]
#define OFF_XT   (OFF_INT + 72*20)     // sXT  [180][20]
#define OFF_HT   (OFF_XT + 180*20)     // sHT  [180][20]
#define OFF_HCT  (OFF_HT + 180*20)     // sHCT [244][20]
#define OFF_OT   (OFF_HCT + 244*20)    // sOT  [180][20]
#define OFF_GH   (OFF_OT + 180*20)     // ghT  [568][18]
#define OFF_GI   (OFF_GH + 568*18)     // giT  [640][18]  (also o1 partials 720*16)
#define OFF_CUR  (OFF_GI + 640*18)     // sCur [16][64]
#define SMEM_FLOATS (OFF_CUR + 16*64)
#define SMEM_BYTES  (SMEM_FLOATS * 4)

__device__ __forceinline__ void tr_slice(const float* src, float* dst, int O, int K,
                                         int start, int stride) {
    for (int i = start; i < O * K; i += stride) {
        int o = i / K, k = i - o * K;
        dst[k * O + o] = src[i];
    }
}

__global__ __launch_bounds__(THREADS, 1)
void rnn_kernel(const float* __restrict__ phys,
                const float* __restrict__ latents,
                const float* __restrict__ W_in, const float* __restrict__ b_in,
                const float* __restrict__ W_hp, const float* __restrict__ b_hp,
                const float* __restrict__ W_ih, const float* __restrict__ b_ih,
                const float* __restrict__ W_hh, const float* __restrict__ b_hh,
                const float* __restrict__ W_o1, const float* __restrict__ b_o1,
                const float* __restrict__ W_o2, const float* __restrict__ b_o2,
                float* __restrict__ out)
{
    extern __shared__ float sm[];
    float* sInT = sm + OFF_INT;
    float* sXT  = sm + OFF_XT;
    float* sHT  = sm + OFF_HT;
    float* sHCT = sm + OFF_HCT;
    float* sOT  = sm + OFF_OT;
    float* ghT  = sm + OFF_GH;
    float* giT  = sm + OFF_GI;
    float* sCur = sm + OFF_CUR;

    const int tid  = threadIdx.x;
    const int wid  = tid >> 5;
    const int lane = tid & 31;
    const int b0   = blockIdx.x * RT;

    // ---------- in-kernel weight transpose + grid barrier ----------
    {
        int start = blockIdx.x * THREADS + tid;
        int stride = NCTA * THREADS;
        tr_slice(W_in, g_WTin, NH, KIN, start, stride);
        tr_slice(W_hp, g_WThp, NH, NL, start, stride);
        tr_slice(W_ih, g_WTih, NH3, NH, start, stride);
        tr_slice(W_hh, g_WThh, NH3, NH, start, stride);
        tr_slice(W_o1, g_WTo1, NH, KO1, start, stride);
        tr_slice(W_o2, g_WTo2, NL, NH, start, stride);
    }
    __syncthreads();
    if (tid == 0) {
        unsigned p = g_rel;
        __threadfence();
        unsigned a = atomicAdd(&g_cnt, 1);
        if (a == NCTA - 1) {
            g_cnt = 0;
            __threadfence();
            g_rel = p + 1;
        } else {
            while (g_rel == p) { }
        }
        __threadfence();
    }
    __syncthreads();

    // ---------- prologue: cur = latents; sInT = [phys0 | cur]; h0 ----------
    for (int i = tid; i < RT * NL; i += THREADS) {
        int r = i & 15, l = i >> 4;
        float v = latents[(size_t)(b0 + r) * NL + l];
        sCur[r * NL + l] = v;
        sInT[(NP + l) * 20 + r] = v;
    }
    if (tid < RT * NP) {
        int r = tid >> 3, p = tid & 7;
        sInT[p * 20 + r] = phys[((size_t)(b0 + r) * NT + 0) * NP + p];
    }
    __syncthreads();
    if (tid < NH) {
        float acc[16];
#pragma unroll
        for (int r = 0; r < 16; r++) acc[r] = 0.0f;
        for (int k = 0; k < NL; k++) {
            float w = g_WThp[k * NH + tid];
#pragma unroll
            for (int r = 0; r < 16; r++)
                acc[r] = fmaf(sCur[r * NL + k], w, acc[r]);
        }
        float bb = b_hp[tid];
#pragma unroll
        for (int r = 0; r < 16; r++) sHT[tid * 20 + r] = acc[r] + bb;
    }
    __syncthreads();

    // ---------- main time loop ----------
#pragma unroll 1
    for (int t = 0; t < NT; t++) {
        // ===== Phase A: gh (cols 0..511 + tail halves) and x =====
        {
            int c2[2] = { tid, tid + 256 };
            u64 acc2[8][2];
            gemm2<NH3, 20, 2>(sHT, g_WThh, c2, 0, NH, acc2);
#pragma unroll
            for (int j = 0; j < 2; j++) {
                float bb = b_hh[c2[j]];
#pragma unroll
                for (int rp = 0; rp < 8; rp++) {
                    float lo, hi;
                    unpk(acc2[rp][j], lo, hi);
                    ghT[c2[j] * 18 + 2 * rp]     = lo + bb;
                    ghT[c2[j] * 18 + 2 * rp + 1] = hi + bb;
                }
            }
        }
        if (wid < 6) {
            // x-gemm: warp w handles cols w*30 + lane (lane<30)
            bool valid = lane < 30;
            int xc = wid * 30 + (valid ? lane : 29);
            int c1[1] = { xc };
            u64 acc1[8][1];
            gemm2<NH, 20, 1>(sInT, g_WTin, c1, 0, KIN, acc1);
            if (valid) {
                float bb = b_in[xc];
#pragma unroll
                for (int rp = 0; rp < 8; rp++) {
                    float lo, hi;
                    unpk(acc1[rp][0], lo, hi);
                    sXT[xc * 20 + 2 * rp]     = gelu_f(lo + bb);
                    sXT[xc * 20 + 2 * rp + 1] = gelu_f(hi + bb);
                }
            }
        } else {
            // gh tail cols 512..539 as K-halves: warp6 = [0,92), warp7 = [92,180)
            bool valid = lane < 28;
            int scol = 512 + (valid ? lane : 27);
            int half = wid - 6;
            int c1[1] = { scol };
            u64 acc1[8][1];
            gemm2<NH3, 20, 1>(sHT, g_WThh, c1, half ? 92 : 0, half ? NH : 92, acc1);
            if (valid) {
                int dcol = half ? (540 + lane) : scol;
                float bb = half ? 0.0f : b_hh[scol];
#pragma unroll
                for (int rp = 0; rp < 8; rp++) {
                    float lo, hi;
                    unpk(acc1[rp][0], lo, hi);
                    ghT[dcol * 18 + 2 * rp]     = lo + bb;
                    ghT[dcol * 18 + 2 * rp + 1] = hi + bb;
                }
            }
        }
        __syncthreads();

        // ===== Phase B: gi (cols 0..511 + tail quarters on warps 0..3) =====
        {
            int c2[2] = { tid, tid + 256 };
            u64 acc2[8][2];
            gemm2<NH3, 20, 2>(sXT, g_WTih, c2, 0, NH, acc2);
#pragma unroll
            for (int j = 0; j < 2; j++) {
                float bb = b_ih[c2[j]];
#pragma unroll
                for (int rp = 0; rp < 8; rp++) {
                    float lo, hi;
                    unpk(acc2[rp][j], lo, hi);
                    giT[c2[j] * 18 + 2 * rp]     = lo + bb;
                    giT[c2[j] * 18 + 2 * rp + 1] = hi + bb;
                }
            }
        }
        if (wid < 4) {
            // quarters: warp w -> k-range q=w over cols 512+lane (lane<28)
            static const int qk0[4] = { 0, 48, 92, 136 };
            static const int qk1[4] = { 48, 92, 136, 180 };
            bool valid = lane < 28;
            int scol = 512 + (valid ? lane : 27);
            int c1[1] = { scol };
            u64 acc1[8][1];
            gemm2<NH3, 20, 1>(sXT, g_WTih, c1, qk0[wid], qk1[wid], acc1);
            if (valid) {
                int dcol = (wid == 0) ? scol : (540 + (wid - 1) * 28 + lane);
                float bb = (wid == 0) ? b_ih[scol] : 0.0f;
#pragma unroll
                for (int rp = 0; rp < 8; rp++) {
                    float lo, hi;
                    unpk(acc1[rp][0], lo, hi);
                    giT[dcol * 18 + 2 * rp]     = lo + bb;
                    giT[dcol * 18 + 2 * rp + 1] = hi + bb;
                }
            }
        }
        __syncthreads();

        // ===== Phase C: gates -> h_new; build sHT, sHCT =====
        for (int i = tid; i < RT * NH; i += THREADS) {
            int r = i & 15, j = i >> 4;
            float gir = giT[j * 18 + r];
            float giz = giT[(NH + j) * 18 + r];
            float gin = giT[(2 * NH + j) * 18 + r];
            float ghr = ghT[j * 18 + r];
            float ghz = ghT[(NH + j) * 18 + r];
            float ghn = ghT[(2 * NH + j) * 18 + r];
            if (j >= 152) {
                int s = j - 152;
                gin += giT[(540 + s) * 18 + r] + giT[(568 + s) * 18 + r]
                     + giT[(596 + s) * 18 + r];
                ghn += ghT[(540 + s) * 18 + r];
            }
            float rr = sigmoid_f(gir + ghr);
            float zz = sigmoid_f(giz + ghz);
            float nn = tanhf(gin + rr * ghn);
            float hn = (1.0f - zz) * nn + zz * sHT[j * 20 + r];
            sHT[j * 20 + r]  = hn;
            sHCT[j * 20 + r] = hn;
        }
        for (int i = tid; i < RT * NL; i += THREADS) {
            int r = i & 15, l = i >> 4;
            sHCT[(NH + l) * 20 + r] = sCur[r * NL + l];
        }
        __syncthreads();

        // ===== Phase D: o1 partials (K-quarters, warp-uniform) =====
        {
            static const int dk0[4] = { 0, 64, 124, 184 };
            static const int dk1[4] = { 64, 124, 184, 244 };
            float* P = giT;   // reuse as [4*180][16] partials
#pragma unroll
            for (int rep = 0; rep < 3; rep++) {
                int R = wid * 3 + rep;          // 0..23
                int q = R / 6, cb = R % 6;
                int col = cb * 32 + lane;
                bool valid = col < NH;
                int cc = valid ? col : NH - 1;
                int c1[1] = { cc };
                u64 acc1[8][1];
                gemm2<NH, 20, 1>(sHCT, g_WTo1, c1, dk0[q], dk1[q], acc1);
                if (valid) {
#pragma unroll
                    for (int rp = 0; rp < 8; rp++) {
                        float lo, hi;
                        unpk(acc1[rp][0], lo, hi);
                        P[(q * NH + col) * 16 + 2 * rp]     = lo;
                        P[(q * NH + col) * 16 + 2 * rp + 1] = hi;
                    }
                }
            }
        }
        __syncthreads();

        // ===== Phase D2: reduce + bias + gelu -> sOT =====
        {
            const float* P = giT;
            for (int i = tid; i < RT * NH; i += THREADS) {
                int r = i & 15, c = i >> 4;
                float v = P[(0 * NH + c) * 16 + r] + P[(1 * NH + c) * 16 + r]
                        + P[(2 * NH + c) * 16 + r] + P[(3 * NH + c) * 16 + r]
                        + b_o1[c];
                sOT[c * 20 + r] = gelu_f(v);
            }
        }
        __syncthreads();

        // ===== Phase E: delta = o @ W_o2^T; cur update; write out; prep sInT =====
        {
            int col = tid & 63;
            int rq  = tid >> 6;     // 4 rows: rq*4 .. rq*4+3
            u64 a0, a1, acc0 = 0ull, acc1 = 0ull;
            float w[4], wn[4];
#pragma unroll
            for (int kk = 0; kk < 4; kk++) w[kk] = g_WTo2[kk * NL + col];
#pragma unroll 1
            for (int k = 0; k < NH; k += 4) {
#pragma unroll
                for (int kk = 0; kk < 4; kk++) wn[kk] = g_WTo2[(k + 4 + kk) * NL + col];
#pragma unroll
                for (int kk = 0; kk < 4; kk++) {
                    fq(sOT + (k + kk) * 20 + rq * 4, a0, a1);
                    u64 wp = dup2(w[kk]);
                    acc0 = ff2(a0, wp, acc0);
                    acc1 = ff2(a1, wp, acc1);
                }
#pragma unroll
                for (int kk = 0; kk < 4; kk++) w[kk] = wn[kk];
            }
            float v[4];
            unpk(acc0, v[0], v[1]);
            unpk(acc1, v[2], v[3]);
            float bb = b_o2[col];
#pragma unroll
            for (int rr = 0; rr < 4; rr++) {
                int row = rq * 4 + rr;
                float c = sCur[row * NL + col] + v[rr] + bb;
                c = fminf(fmaxf(c, 0.0f), 1.0f);
                sCur[row * NL + col] = c;
                sInT[(NP + col) * 20 + row] = c;
                out[((size_t)(b0 + row) * NT + t) * NL + col] = c;
            }
        }
        if (tid < RT * NP && t + 1 < NT) {
            int r = tid >> 3, p = tid & 7;
            sInT[p * 20 + r] = phys[((size_t)(b0 + r) * NT + t + 1) * NP + p];
        }
        __syncthreads();
    }
}

extern "C" void kernel_launch(void* const* d_in, const int* in_sizes, int n_in,
                              void* d_out, int out_size)
{
    const float* phys    = (const float*)d_in[0];
    const float* latents = (const float*)d_in[1];
    const float* W_in    = (const float*)d_in[2];
    const float* b_in    = (const float*)d_in[3];
    const float* W_hp    = (const float*)d_in[4];
    const float* b_hp    = (const float*)d_in[5];
    const float* W_ih    = (const float*)d_in[6];
    const float* b_ih    = (const float*)d_in[7];
    const float* W_hh    = (const float*)d_in[8];
    const float* b_hh    = (const float*)d_in[9];
    const float* W_o1    = (const float*)d_in[10];
    const float* b_o1    = (const float*)d_in[11];
    const float* W_o2    = (const float*)d_in[12];
    const float* b_o2    = (const float*)d_in[13];
    float* out = (float*)d_out;

    cudaFuncSetAttribute(rnn_kernel,
                         cudaFuncAttributeMaxDynamicSharedMemorySize, SMEM_BYTES);
    rnn_kernel<<<NCTA, THREADS, SMEM_BYTES>>>(phys, latents,
                                              W_in, b_in, W_hp, b_hp,
                                              W_ih, b_ih, W_hh, b_hh,
                                              W_o1, b_o1, W_o2, b_o2, out);
}

// round 5
// speedup vs baseline: 1.5176x; 1.5176x over previous
#include <cuda_runtime.h>
#include <math.h>

// Problem dims
#define NB 2048
#define NT 512
#define NP 8
#define NL 64
#define NH 180
#define NH3 540
#define KIN (NP+NL)     // 72
#define KO1 (NH+NL)     // 244

#define RT 16           // batch rows per CTA
#define NCTA (NB/RT)    // 128
#define THREADS 256

typedef unsigned long long u64;

// -------- K-major (transposed) weights, padded by 4 k-rows for prefetch ----
__device__ float g_WTin[(KIN+4)*NH];
__device__ float g_WThp[(NL+4)*NH];
__device__ float g_WTih[(NH+4)*NH3];
__device__ float g_WThh[(NH+4)*NH3];
__device__ float g_WTo1[(KO1+4)*NH];
__device__ float g_WTo2[(NH+4)*NL];

// grid barrier state
__device__ unsigned g_cnt = 0;
__device__ volatile unsigned g_rel = 0;

__device__ __forceinline__ u64 ff2(u64 a, u64 b, u64 c) {
    u64 d;
    asm("fma.rn.f32x2 %0, %1, %2, %3;" : "=l"(d) : "l"(a), "l"(b), "l"(c));
    return d;
}
__device__ __forceinline__ u64 dup2(float w) {
    u64 d;
    asm("mov.b64 %0, {%1, %1};" : "=l"(d) : "f"(w), "f"(w));
    return d;
}
__device__ __forceinline__ void unpk(u64 p, float& lo, float& hi) {
    asm("mov.b64 {%0, %1}, %2;" : "=f"(lo), "=f"(hi) : "l"(p));
}
__device__ __forceinline__ void fq(const float* p, u64& a, u64& b) {
    double2 q = *reinterpret_cast<const double2*>(p);
    a = __double_as_longlong(q.x);
    b = __double_as_longlong(q.y);
}
__device__ __forceinline__ float gelu_f(float x) {
    return 0.5f * x * (1.0f + erff(x * 0.7071067811865476f));
}
__device__ __forceinline__ float sigmoid_f(float x) {
    return 1.0f / (1.0f + expf(-x));
}

// acc[rp][j] += A_pairs * W[:,c[j]] over k in [k0,k1). A is k-major, STRIDE floats/row.
template<int O, int STRIDE, int NC>
__device__ __forceinline__ void gemm2(const float* __restrict__ sAT,
                                      const float* __restrict__ W,
                                      const int* c, int k0, int k1,
                                      u64 (&acc)[8][NC])
{
#pragma unroll
    for (int rp = 0; rp < 8; rp++)
#pragma unroll
        for (int j = 0; j < NC; j++) acc[rp][j] = 0ull;

    float w[4][NC];
#pragma unroll
    for (int kk = 0; kk < 4; kk++)
#pragma unroll
        for (int j = 0; j < NC; j++) w[kk][j] = W[(k0 + kk) * O + c[j]];

#pragma unroll 1
    for (int k = k0; k < k1; k += 4) {
        float wn[4][NC];
#pragma unroll
        for (int kk = 0; kk < 4; kk++)
#pragma unroll
            for (int j = 0; j < NC; j++) wn[kk][j] = W[(k + 4 + kk) * O + c[j]];
#pragma unroll
        for (int kk = 0; kk < 4; kk++) {
            u64 a[8];
            const float* ap = sAT + (k + kk) * STRIDE;
            fq(ap + 0,  a[0], a[1]);
            fq(ap + 4,  a[2], a[3]);
            fq(ap + 8,  a[4], a[5]);
            fq(ap + 12, a[6], a[7]);
#pragma unroll
            for (int j = 0; j < NC; j++) {
                u64 wp = dup2(w[kk][j]);
#pragma unroll
                for (int rp = 0; rp < 8; rp++)
                    acc[rp][j] = ff2(a[rp], wp, acc[rp][j]);
            }
        }
#pragma unroll
        for (int kk = 0; kk < 4; kk++)
#pragma unroll
            for (int j = 0; j < NC; j++) w[kk][j] = wn[kk][j];
    }
}

// SMEM layout (floats)
#define OFF_INT  0                     // sInT [72][20]
#define OFF_XT   (OFF_INT + 72*20)     // sXT  [180][20]
#define OFF_HT   (OFF_XT + 180*20)     // sHT  [180][20]
#define OFF_HCT  (OFF_HT + 180*20)     // sHCT [244][20]
#define OFF_OT   (OFF_HCT + 244*20)    // sOT  [180][20]
#define OFF_GH   (OFF_OT + 180*20)     // ghT  [568][18]
#define OFF_GI   (OFF_GH + 568*18)     // giT  [640][18]  (also o1 partials 720*16)
#define OFF_CUR  (OFF_GI + 640*18)     // sCur [16][64]
#define SMEM_FLOATS (OFF_CUR + 16*64)
#define SMEM_BYTES  (SMEM_FLOATS * 4)

__device__ __forceinline__ void tr_slice(const float* src, float* dst, int O, int K,
                                         int start, int stride) {
    for (int i = start; i < O * K; i += stride) {
        int o = i / K, k = i - o * K;
        dst[k * O + o] = src[i];
    }
}

__global__ __launch_bounds__(THREADS, 1)
void rnn_kernel(const float* __restrict__ phys,
                const float* __restrict__ latents,
                const float* __restrict__ W_in, const float* __restrict__ b_in,
                const float* __restrict__ W_hp, const float* __restrict__ b_hp,
                const float* __restrict__ W_ih, const float* __restrict__ b_ih,
                const float* __restrict__ W_hh, const float* __restrict__ b_hh,
                const float* __restrict__ W_o1, const float* __restrict__ b_o1,
                const float* __restrict__ W_o2, const float* __restrict__ b_o2,
                float* __restrict__ out)
{
    extern __shared__ float sm[];
    float* sInT = sm + OFF_INT;
    float* sXT  = sm + OFF_XT;
    float* sHT  = sm + OFF_HT;
    float* sHCT = sm + OFF_HCT;
    float* sOT  = sm + OFF_OT;
    float* ghT  = sm + OFF_GH;
    float* giT  = sm + OFF_GI;
    float* sCur = sm + OFF_CUR;

    const int tid  = threadIdx.x;
    const int wid  = tid >> 5;
    const int lane = tid & 31;
    const int b0   = blockIdx.x * RT;

    // ---------- in-kernel weight transpose + grid barrier ----------
    {
        int start = blockIdx.x * THREADS + tid;
        int stride = NCTA * THREADS;
        tr_slice(W_in, g_WTin, NH, KIN, start, stride);
        tr_slice(W_hp, g_WThp, NH, NL, start, stride);
        tr_slice(W_ih, g_WTih, NH3, NH, start, stride);
        tr_slice(W_hh, g_WThh, NH3, NH, start, stride);
        tr_slice(W_o1, g_WTo1, NH, KO1, start, stride);
        tr_slice(W_o2, g_WTo2, NL, NH, start, stride);
    }
    __syncthreads();
    if (tid == 0) {
        unsigned p = g_rel;
        __threadfence();
        unsigned a = atomicAdd(&g_cnt, 1);
        if (a == NCTA - 1) {
            g_cnt = 0;
            __threadfence();
            g_rel = p + 1;
        } else {
            while (g_rel == p) { }
        }
        __threadfence();
    }
    __syncthreads();

    // ---------- prologue: cur = latents; sInT = [phys0 | cur]; h0 ----------
    for (int i = tid; i < RT * NL; i += THREADS) {
        int r = i & 15, l = i >> 4;
        float v = latents[(size_t)(b0 + r) * NL + l];
        sCur[r * NL + l] = v;
        sInT[(NP + l) * 20 + r] = v;
    }
    if (tid < RT * NP) {
        int r = tid >> 3, p = tid & 7;
        sInT[p * 20 + r] = phys[((size_t)(b0 + r) * NT + 0) * NP + p];
    }
    __syncthreads();
    if (tid < NH) {
        float acc[16];
#pragma unroll
        for (int r = 0; r < 16; r++) acc[r] = 0.0f;
        for (int k = 0; k < NL; k++) {
            float w = g_WThp[k * NH + tid];
#pragma unroll
            for (int r = 0; r < 16; r++)
                acc[r] = fmaf(sCur[r * NL + k], w, acc[r]);
        }
        float bb = b_hp[tid];
#pragma unroll
        for (int r = 0; r < 16; r++) sHT[tid * 20 + r] = acc[r] + bb;
    }
    __syncthreads();

    // ---------- main time loop ----------
#pragma unroll 1
    for (int t = 0; t < NT; t++) {
        // ===== Phase A: gh (cols 0..511 + tail halves) and x =====
        {
            int c2[2] = { tid, tid + 256 };
            u64 acc2[8][2];
            gemm2<NH3, 20, 2>(sHT, g_WThh, c2, 0, NH, acc2);
#pragma unroll
            for (int j = 0; j < 2; j++) {
                float bb = b_hh[c2[j]];
#pragma unroll
                for (int rp = 0; rp < 8; rp++) {
                    float lo, hi;
                    unpk(acc2[rp][j], lo, hi);
                    ghT[c2[j] * 18 + 2 * rp]     = lo + bb;
                    ghT[c2[j] * 18 + 2 * rp + 1] = hi + bb;
                }
            }
        }
        if (wid < 6) {
            // x-gemm: warp w handles cols w*30 + lane (lane<30)
            bool valid = lane < 30;
            int xc = wid * 30 + (valid ? lane : 29);
            int c1[1] = { xc };
            u64 acc1[8][1];
            gemm2<NH, 20, 1>(sInT, g_WTin, c1, 0, KIN, acc1);
            if (valid) {
                float bb = b_in[xc];
#pragma unroll
                for (int rp = 0; rp < 8; rp++) {
                    float lo, hi;
                    unpk(acc1[rp][0], lo, hi);
                    sXT[xc * 20 + 2 * rp]     = gelu_f(lo + bb);
                    sXT[xc * 20 + 2 * rp + 1] = gelu_f(hi + bb);
                }
            }
        } else {
            // gh tail cols 512..539 as K-halves: warp6 = [0,92), warp7 = [92,180)
            bool valid = lane < 28;
            int scol = 512 + (valid ? lane : 27);
            int half = wid - 6;
            int c1[1] = { scol };
            u64 acc1[8][1];
            gemm2<NH3, 20, 1>(sHT, g_WThh, c1, half ? 92 : 0, half ? NH : 92, acc1);
            if (valid) {
                int dcol = half ? (540 + lane) : scol;
                float bb = half ? 0.0f : b_hh[scol];
#pragma unroll
                for (int rp = 0; rp < 8; rp++) {
                    float lo, hi;
                    unpk(acc1[rp][0], lo, hi);
                    ghT[dcol * 18 + 2 * rp]     = lo + bb;
                    ghT[dcol * 18 + 2 * rp + 1] = hi + bb;
                }
            }
        }
        __syncthreads();

        // ===== Phase B: gi (cols 0..511 + tail quarters on warps 0..3) =====
        {
            int c2[2] = { tid, tid + 256 };
            u64 acc2[8][2];
            gemm2<NH3, 20, 2>(sXT, g_WTih, c2, 0, NH, acc2);
#pragma unroll
            for (int j = 0; j < 2; j++) {
                float bb = b_ih[c2[j]];
#pragma unroll
                for (int rp = 0; rp < 8; rp++) {
                    float lo, hi;
                    unpk(acc2[rp][j], lo, hi);
                    giT[c2[j] * 18 + 2 * rp]     = lo + bb;
                    giT[c2[j] * 18 + 2 * rp + 1] = hi + bb;
                }
            }
        }
        if (wid < 4) {
            // quarters: warp w -> k-range q=w over cols 512+lane (lane<28)
            static const int qk0[4] = { 0, 48, 92, 136 };
            static const int qk1[4] = { 48, 92, 136, 180 };
            bool valid = lane < 28;
            int scol = 512 + (valid ? lane : 27);
            int c1[1] = { scol };
            u64 acc1[8][1];
            gemm2<NH3, 20, 1>(sXT, g_WTih, c1, qk0[wid], qk1[wid], acc1);
            if (valid) {
                int dcol = (wid == 0) ? scol : (540 + (wid - 1) * 28 + lane);
                float bb = (wid == 0) ? b_ih[scol] : 0.0f;
#pragma unroll
                for (int rp = 0; rp < 8; rp++) {
                    float lo, hi;
                    unpk(acc1[rp][0], lo, hi);
                    giT[dcol * 18 + 2 * rp]     = lo + bb;
                    giT[dcol * 18 + 2 * rp + 1] = hi + bb;
                }
            }
        }
        __syncthreads();

        // ===== Phase C: gates -> h_new; build sHT, sHCT =====
        for (int i = tid; i < RT * NH; i += THREADS) {
            int r = i & 15, j = i >> 4;
            float gir = giT[j * 18 + r];
            float giz = giT[(NH + j) * 18 + r];
            float gin = giT[(2 * NH + j) * 18 + r];
            float ghr = ghT[j * 18 + r];
            float ghz = ghT[(NH + j) * 18 + r];
            float ghn = ghT[(2 * NH + j) * 18 + r];
            if (j >= 152) {
                int s = j - 152;
                gin += giT[(540 + s) * 18 + r] + giT[(568 + s) * 18 + r]
                     + giT[(596 + s) * 18 + r];
                ghn += ghT[(540 + s) * 18 + r];
            }
            float rr = sigmoid_f(gir + ghr);
            float zz = sigmoid_f(giz + ghz);
            float nn = tanhf(gin + rr * ghn);
            float hn = (1.0f - zz) * nn + zz * sHT[j * 20 + r];
            sHT[j * 20 + r]  = hn;
            sHCT[j * 20 + r] = hn;
        }
        for (int i = tid; i < RT * NL; i += THREADS) {
            int r = i & 15, l = i >> 4;
            sHCT[(NH + l) * 20 + r] = sCur[r * NL + l];
        }
        __syncthreads();

        // ===== Phase D: o1 partials (K-quarters, warp-uniform) =====
        {
            static const int dk0[4] = { 0, 64, 124, 184 };
            static const int dk1[4] = { 64, 124, 184, 244 };
            float* P = giT;   // reuse as [4*180][16] partials
#pragma unroll
            for (int rep = 0; rep < 3; rep++) {
                int R = wid * 3 + rep;          // 0..23
                int q = R / 6, cb = R % 6;
                int col = cb * 32 + lane;
                bool valid = col < NH;
                int cc = valid ? col : NH - 1;
                int c1[1] = { cc };
                u64 acc1[8][1];
                gemm2<NH, 20, 1>(sHCT, g_WTo1, c1, dk0[q], dk1[q], acc1);
                if (valid) {
#pragma unroll
                    for (int rp = 0; rp < 8; rp++) {
                        float lo, hi;
                        unpk(acc1[rp][0], lo, hi);
                        P[(q * NH + col) * 16 + 2 * rp]     = lo;
                        P[(q * NH + col) * 16 + 2 * rp + 1] = hi;
                    }
                }
            }
        }
        __syncthreads();

        // ===== Phase D2: reduce + bias + gelu -> sOT =====
        {
            const float* P = giT;
            for (int i = tid; i < RT * NH; i += THREADS) {
                int r = i & 15, c = i >> 4;
                float v = P[(0 * NH + c) * 16 + r] + P[(1 * NH + c) * 16 + r]
                        + P[(2 * NH + c) * 16 + r] + P[(3 * NH + c) * 16 + r]
                        + b_o1[c];
                sOT[c * 20 + r] = gelu_f(v);
            }
        }
        __syncthreads();

        // ===== Phase E: delta = o @ W_o2^T; cur update; write out; prep sInT =====
        {
            int col = tid & 63;
            int rq  = tid >> 6;     // 4 rows: rq*4 .. rq*4+3
            u64 a0, a1, acc0 = 0ull, acc1 = 0ull;
            float w[4], wn[4];
#pragma unroll
            for (int kk = 0; kk < 4; kk++) w[kk] = g_WTo2[kk * NL + col];
#pragma unroll 1
            for (int k = 0; k < NH; k += 4) {
#pragma unroll
                for (int kk = 0; kk < 4; kk++) wn[kk] = g_WTo2[(k + 4 + kk) * NL + col];
#pragma unroll
                for (int kk = 0; kk < 4; kk++) {
                    fq(sOT + (k + kk) * 20 + rq * 4, a0, a1);
                    u64 wp = dup2(w[kk]);
                    acc0 = ff2(a0, wp, acc0);
                    acc1 = ff2(a1, wp, acc1);
                }
#pragma unroll
                for (int kk = 0; kk < 4; kk++) w[kk] = wn[kk];
            }
            float v[4];
            unpk(acc0, v[0], v[1]);
            unpk(acc1, v[2], v[3]);
            float bb = b_o2[col];
#pragma unroll
            for (int rr = 0; rr < 4; rr++) {
                int row = rq * 4 + rr;
                float c = sCur[row * NL + col] + v[rr] + bb;
                c = fminf(fmaxf(c, 0.0f), 1.0f);
                sCur[row * NL + col] = c;
                sInT[(NP + col) * 20 + row] = c;
                out[((size_t)(b0 + row) * NT + t) * NL + col] = c;
            }
        }
        if (tid < RT * NP && t + 1 < NT) {
            int r = tid >> 3, p = tid & 7;
            sInT[p * 20 + r] = phys[((size_t)(b0 + r) * NT + t + 1) * NP + p];
        }
        __syncthreads();
    }
}

extern "C" void kernel_launch(void* const* d_in, const int* in_sizes, int n_in,
                              void* d_out, int out_size)
{
    const float* phys    = (const float*)d_in[0];
    const float* latents = (const float*)d_in[1];
    const float* W_in    = (const float*)d_in[2];
    const float* b_in    = (const float*)d_in[3];
    const float* W_hp    = (const float*)d_in[4];
    const float* b_hp    = (const float*)d_in[5];
    const float* W_ih    = (const float*)d_in[6];
    const float* b_ih    = (const float*)d_in[7];
    const float* W_hh    = (const float*)d_in[8];
    const float* b_hh    = (const float*)d_in[9];
    const float* W_o1    = (const float*)d_in[10];
    const float* b_o1    = (const float*)d_in[11];
    const float* W_o2    = (const float*)d_in[12];
    const float* b_o2    = (const float*)d_in[13];
    float* out = (float*)d_out;

    cudaFuncSetAttribute(rnn_kernel,
                         cudaFuncAttributeMaxDynamicSharedMemorySize, SMEM_BYTES);
    rnn_kernel<<<NCTA, THREADS, SMEM_BYTES>>>(phys, latents,
                                              W_in, b_in, W_hp, b_hp,
                                              W_ih, b_ih, W_hh, b_hh,
                                              W_o1, b_o1, W_o2, b_o2, out);
}

// round 6
// speedup vs baseline: 1.9704x; 1.2984x over previous
#include <cuda_runtime.h>
#include <math.h>

// Problem dims
#define NB 2048
#define NT 512
#define NP 8
#define NL 64
#define NH 180
#define NH3 540
#define KIN (NP+NL)     // 72
#define KO1 (NH+NL)     // 244
#define KPAD 24

#define RT 16           // batch rows per CTA
#define NCTA (NB/RT)    // 128
#define THREADS 256

typedef unsigned long long u64;

// -------- K-major (transposed) weights, padded k-rows for deep prefetch ----
__device__ float g_WTin[(KIN+KPAD)*NH];
__device__ float g_WThp[(NL+KPAD)*NH];
__device__ float g_WTih[(NH+KPAD)*NH3];
__device__ float g_WThh[(NH+KPAD)*NH3];
__device__ float g_WTo1[(KO1+KPAD)*NH];
__device__ float g_WTo2[(NH+KPAD)*NL];

// grid barrier state
__device__ unsigned g_cnt = 0;
__device__ volatile unsigned g_rel = 0;

__device__ __forceinline__ u64 ff2(u64 a, u64 b, u64 c) {
    u64 d;
    asm("fma.rn.f32x2 %0, %1, %2, %3;" : "=l"(d) : "l"(a), "l"(b), "l"(c));
    return d;
}
__device__ __forceinline__ u64 dup2(float w) {
    u64 d;
    asm("mov.b64 %0, {%1, %1};" : "=l"(d) : "f"(w), "f"(w));
    return d;
}
__device__ __forceinline__ void unpk(u64 p, float& lo, float& hi) {
    asm("mov.b64 {%0, %1}, %2;" : "=f"(lo), "=f"(hi) : "l"(p));
}
__device__ __forceinline__ void fq(const float* p, u64& a, u64& b) {
    double2 q = *reinterpret_cast<const double2*>(p);
    a = __double_as_longlong(q.x);
    b = __double_as_longlong(q.y);
}
__device__ __forceinline__ float gelu_f(float x) {
    return 0.5f * x * (1.0f + erff(x * 0.7071067811865476f));
}
__device__ __forceinline__ float sigmoid_f(float x) {
    return 1.0f / (1.0f + expf(-x));
}

// ---- weight fetch helpers ----
template<int O>
__device__ __forceinline__ void lw4p(const float* Wc, int k, float2 (&w)[4]) {
#pragma unroll
    for (int i = 0; i < 4; i++)
        w[i] = *reinterpret_cast<const float2*>(Wc + (size_t)(k + i) * O);
}
template<int O>
__device__ __forceinline__ void lw4s(const float* Wc, int k, float (&w)[4]) {
#pragma unroll
    for (int i = 0; i < 4; i++)
        w[i] = Wc[(size_t)(k + i) * O];
}

// ---- compute-chunk helpers (4 k's) ----
template<int STRIDE>
__device__ __forceinline__ void cc_pair(const float* sATk, const float2 (&w)[4],
                                        u64 (&acc)[8][2]) {
#pragma unroll
    for (int kk = 0; kk < 4; kk++) {
        u64 a[8];
        const float* ap = sATk + kk * STRIDE;
        fq(ap + 0,  a[0], a[1]);
        fq(ap + 4,  a[2], a[3]);
        fq(ap + 8,  a[4], a[5]);
        fq(ap + 12, a[6], a[7]);
        u64 wx = dup2(w[kk].x);
        u64 wy = dup2(w[kk].y);
#pragma unroll
        for (int rp = 0; rp < 8; rp++) acc[rp][0] = ff2(a[rp], wx, acc[rp][0]);
#pragma unroll
        for (int rp = 0; rp < 8; rp++) acc[rp][1] = ff2(a[rp], wy, acc[rp][1]);
    }
}
template<int STRIDE>
__device__ __forceinline__ void cc_sing(const float* sATk, const float (&w)[4],
                                        u64 (&acc)[8]) {
#pragma unroll
    for (int kk = 0; kk < 4; kk++) {
        u64 a[8];
        const float* ap = sATk + kk * STRIDE;
        fq(ap + 0,  a[0], a[1]);
        fq(ap + 4,  a[2], a[3]);
        fq(ap + 8,  a[4], a[5]);
        fq(ap + 12, a[6], a[7]);
        u64 wp = dup2(w[kk]);
#pragma unroll
        for (int rp = 0; rp < 8; rp++) acc[rp] = ff2(a[rp], wp, acc[rp]);
    }
}

// ---- pipelined pair GEMM over full K (compile-time), cols {col0, col0+1} ----
template<int K, int O, int STRIDE>
__device__ __forceinline__ void gemm_pair(const float* __restrict__ sAT,
                                          const float* __restrict__ W,
                                          int col0, u64 (&acc)[8][2]) {
#pragma unroll
    for (int rp = 0; rp < 8; rp++) { acc[rp][0] = 0ull; acc[rp][1] = 0ull; }
    const float* Wc = W + col0;
    float2 w0[4], w1[4], w2[4], w3[4];
    lw4p<O>(Wc, 0, w0);
    lw4p<O>(Wc, 4, w1);
    lw4p<O>(Wc, 8, w2);
    int k = 0;
#pragma unroll 1
    for (; k + 16 <= K; k += 16) {
        lw4p<O>(Wc, k + 12, w3); cc_pair<STRIDE>(sAT + k * STRIDE, w0, acc);
        lw4p<O>(Wc, k + 16, w0); cc_pair<STRIDE>(sAT + (k + 4) * STRIDE, w1, acc);
        lw4p<O>(Wc, k + 20, w1); cc_pair<STRIDE>(sAT + (k + 8) * STRIDE, w2, acc);
        lw4p<O>(Wc, k + 24, w2); cc_pair<STRIDE>(sAT + (k + 12) * STRIDE, w3, acc);
    }
    if (K - k >= 4)  cc_pair<STRIDE>(sAT + k * STRIDE, w0, acc);
    if (K - k >= 8)  cc_pair<STRIDE>(sAT + (k + 4) * STRIDE, w1, acc);
    if (K - k >= 12) cc_pair<STRIDE>(sAT + (k + 8) * STRIDE, w2, acc);
}

// ---- pipelined single-col GEMM over runtime [k0,k1), (k1-k0)%4==0 ----
template<int O, int STRIDE>
__device__ __forceinline__ void gemm_sing(const float* __restrict__ sAT,
                                          const float* __restrict__ W,
                                          int col, int k0, int k1, u64 (&acc)[8]) {
#pragma unroll
    for (int rp = 0; rp < 8; rp++) acc[rp] = 0ull;
    const float* Wc = W + col;
    float w0[4], w1[4], w2[4], w3[4];
    lw4s<O>(Wc, k0, w0);
    lw4s<O>(Wc, k0 + 4, w1);
    lw4s<O>(Wc, k0 + 8, w2);
    int k = k0;
#pragma unroll 1
    for (; k + 16 <= k1; k += 16) {
        lw4s<O>(Wc, k + 12, w3); cc_sing<STRIDE>(sAT + k * STRIDE, w0, acc);
        lw4s<O>(Wc, k + 16, w0); cc_sing<STRIDE>(sAT + (k + 4) * STRIDE, w1, acc);
        lw4s<O>(Wc, k + 20, w1); cc_sing<STRIDE>(sAT + (k + 8) * STRIDE, w2, acc);
        lw4s<O>(Wc, k + 24, w2); cc_sing<STRIDE>(sAT + (k + 12) * STRIDE, w3, acc);
    }
    if (k1 - k >= 4)  cc_sing<STRIDE>(sAT + k * STRIDE, w0, acc);
    if (k1 - k >= 8)  cc_sing<STRIDE>(sAT + (k + 4) * STRIDE, w1, acc);
    if (k1 - k >= 12) cc_sing<STRIDE>(sAT + (k + 8) * STRIDE, w2, acc);
}

// SMEM layout (floats)
#define OFF_INT  0                     // sInT [72][20]
#define OFF_XT   (OFF_INT + 72*20)     // sXT  [180][20]
#define OFF_HT   (OFF_XT + 180*20)     // sHT  [180][20]
#define OFF_HCT  (OFF_HT + 180*20)     // sHCT [244][20]
#define OFF_OT   (OFF_HCT + 244*20)    // sOT  [180][20]
#define OFF_GH   (OFF_OT + 180*20)     // ghT  [568][18]
#define OFF_GI   (OFF_GH + 568*18)     // giT  [640][18]  (reused as o1 partials [720][16])
#define OFF_CUR  (OFF_GI + 640*18)     // sCur [16][64]
#define SMEM_FLOATS (OFF_CUR + 16*64)
#define SMEM_BYTES  (SMEM_FLOATS * 4)

__device__ __forceinline__ void tr_slice(const float* src, float* dst, int O, int K,
                                         int start, int stride) {
    for (int i = start; i < O * K; i += stride) {
        int o = i / K, k = i - o * K;
        dst[k * O + o] = src[i];
    }
}

__global__ __launch_bounds__(THREADS, 1)
void rnn_kernel(const float* __restrict__ phys,
                const float* __restrict__ latents,
                const float* __restrict__ W_in, const float* __restrict__ b_in,
                const float* __restrict__ W_hp, const float* __restrict__ b_hp,
                const float* __restrict__ W_ih, const float* __restrict__ b_ih,
                const float* __restrict__ W_hh, const float* __restrict__ b_hh,
                const float* __restrict__ W_o1, const float* __restrict__ b_o1,
                const float* __restrict__ W_o2, const float* __restrict__ b_o2,
                float* __restrict__ out)
{
    extern __shared__ float sm[];
    float* sInT = sm + OFF_INT;
    float* sXT  = sm + OFF_XT;
    float* sHT  = sm + OFF_HT;
    float* sHCT = sm + OFF_HCT;
    float* sOT  = sm + OFF_OT;
    float* ghT  = sm + OFF_GH;
    float* giT  = sm + OFF_GI;
    float* sCur = sm + OFF_CUR;

    const int tid  = threadIdx.x;
    const int wid  = tid >> 5;
    const int lane = tid & 31;
    const int b0   = blockIdx.x * RT;

    // ---------- in-kernel weight transpose + grid barrier ----------
    {
        int start = blockIdx.x * THREADS + tid;
        int stride = NCTA * THREADS;
        tr_slice(W_in, g_WTin, NH, KIN, start, stride);
        tr_slice(W_hp, g_WThp, NH, NL, start, stride);
        tr_slice(W_ih, g_WTih, NH3, NH, start, stride);
        tr_slice(W_hh, g_WThh, NH3, NH, start, stride);
        tr_slice(W_o1, g_WTo1, NH, KO1, start, stride);
        tr_slice(W_o2, g_WTo2, NL, NH, start, stride);
    }
    __syncthreads();
    if (tid == 0) {
        unsigned p = g_rel;
        __threadfence();
        unsigned a = atomicAdd(&g_cnt, 1);
        if (a == NCTA - 1) {
            g_cnt = 0;
            __threadfence();
            g_rel = p + 1;
        } else {
            while (g_rel == p) { }
        }
        __threadfence();
    }
    __syncthreads();

    // ---------- prologue: cur = latents; sInT = [phys0 | cur]; h0 ----------
    for (int i = tid; i < RT * NL; i += THREADS) {
        int r = i & 15, l = i >> 4;
        float v = latents[(size_t)(b0 + r) * NL + l];
        sCur[r * NL + l] = v;
        sInT[(NP + l) * 20 + r] = v;
    }
    if (tid < RT * NP) {
        int r = tid >> 3, p = tid & 7;
        sInT[p * 20 + r] = phys[((size_t)(b0 + r) * NT + 0) * NP + p];
    }
    __syncthreads();
    if (tid < NH) {
        float acc[16];
#pragma unroll
        for (int r = 0; r < 16; r++) acc[r] = 0.0f;
        for (int k = 0; k < NL; k++) {
            float w = g_WThp[k * NH + tid];
#pragma unroll
            for (int r = 0; r < 16; r++)
                acc[r] = fmaf(sCur[r * NL + k], w, acc[r]);
        }
        float bb = b_hp[tid];
#pragma unroll
        for (int r = 0; r < 16; r++) sHT[tid * 20 + r] = acc[r] + bb;
    }
    __syncthreads();

    // ---------- main time loop ----------
#pragma unroll 1
    for (int t = 0; t < NT; t++) {
        // ===== Phase A: gh (cols 2t,2t+1 pairs + tail halves) and x =====
        {
            u64 acc2[8][2];
            gemm_pair<NH, NH3, 20>(sHT, g_WThh, 2 * tid, acc2);
            float2 bb = *reinterpret_cast<const float2*>(b_hh + 2 * tid);
#pragma unroll
            for (int rp = 0; rp < 8; rp++) {
                float lo, hi;
                unpk(acc2[rp][0], lo, hi);
                ghT[(2 * tid) * 18 + 2 * rp]     = lo + bb.x;
                ghT[(2 * tid) * 18 + 2 * rp + 1] = hi + bb.x;
                unpk(acc2[rp][1], lo, hi);
                ghT[(2 * tid + 1) * 18 + 2 * rp]     = lo + bb.y;
                ghT[(2 * tid + 1) * 18 + 2 * rp + 1] = hi + bb.y;
            }
        }
        if (wid < 6) {
            // x-gemm: warp w handles col w*30 + lane (lane<30)
            bool valid = lane < 30;
            int xc = wid * 30 + (valid ? lane : 29);
            u64 acc1[8];
            gemm_sing<NH, 20>(sInT, g_WTin, xc, 0, KIN, acc1);
            if (valid) {
                float bb = b_in[xc];
#pragma unroll
                for (int rp = 0; rp < 8; rp++) {
                    float lo, hi;
                    unpk(acc1[rp], lo, hi);
                    sXT[xc * 20 + 2 * rp]     = gelu_f(lo + bb);
                    sXT[xc * 20 + 2 * rp + 1] = gelu_f(hi + bb);
                }
            }
        } else {
            // gh tail cols 512..539 as K-halves: warp6 = [0,92), warp7 = [92,180)
            bool valid = lane < 28;
            int scol = 512 + (valid ? lane : 27);
            int half = wid - 6;
            u64 acc1[8];
            gemm_sing<NH3, 20>(sHT, g_WThh, scol, half ? 92 : 0, half ? NH : 92, acc1);
            if (valid) {
                int dcol = half ? (540 + lane) : scol;
                float bb = half ? 0.0f : b_hh[scol];
#pragma unroll
                for (int rp = 0; rp < 8; rp++) {
                    float lo, hi;
                    unpk(acc1[rp], lo, hi);
                    ghT[dcol * 18 + 2 * rp]     = lo + bb;
                    ghT[dcol * 18 + 2 * rp + 1] = hi + bb;
                }
            }
        }
        __syncthreads();

        // ===== Phase B: gi (pairs + tail quarters on warps 0..3) =====
        {
            u64 acc2[8][2];
            gemm_pair<NH, NH3, 20>(sXT, g_WTih, 2 * tid, acc2);
            float2 bb = *reinterpret_cast<const float2*>(b_ih + 2 * tid);
#pragma unroll
            for (int rp = 0; rp < 8; rp++) {
                float lo, hi;
                unpk(acc2[rp][0], lo, hi);
                giT[(2 * tid) * 18 + 2 * rp]     = lo + bb.x;
                giT[(2 * tid) * 18 + 2 * rp + 1] = hi + bb.x;
                unpk(acc2[rp][1], lo, hi);
                giT[(2 * tid + 1) * 18 + 2 * rp]     = lo + bb.y;
                giT[(2 * tid + 1) * 18 + 2 * rp + 1] = hi + bb.y;
            }
        }
        if (wid < 4) {
            static const int qk0[4] = { 0, 48, 92, 136 };
            static const int qk1[4] = { 48, 92, 136, 180 };
            bool valid = lane < 28;
            int scol = 512 + (valid ? lane : 27);
            u64 acc1[8];
            gemm_sing<NH3, 20>(sXT, g_WTih, scol, qk0[wid], qk1[wid], acc1);
            if (valid) {
                int dcol = (wid == 0) ? scol : (540 + (wid - 1) * 28 + lane);
                float bb = (wid == 0) ? b_ih[scol] : 0.0f;
#pragma unroll
                for (int rp = 0; rp < 8; rp++) {
                    float lo, hi;
                    unpk(acc1[rp], lo, hi);
                    giT[dcol * 18 + 2 * rp]     = lo + bb;
                    giT[dcol * 18 + 2 * rp + 1] = hi + bb;
                }
            }
        }
        __syncthreads();

        // ===== Phase C: gates -> h_new; build sHT, sHCT =====
        for (int i = tid; i < RT * NH; i += THREADS) {
            int r = i & 15, j = i >> 4;
            float gir = giT[j * 18 + r];
            float giz = giT[(NH + j) * 18 + r];
            float gin = giT[(2 * NH + j) * 18 + r];
            float ghr = ghT[j * 18 + r];
            float ghz = ghT[(NH + j) * 18 + r];
            float ghn = ghT[(2 * NH + j) * 18 + r];
            if (j >= 152) {
                int s = j - 152;
                gin += giT[(540 + s) * 18 + r] + giT[(568 + s) * 18 + r]
                     + giT[(596 + s) * 18 + r];
                ghn += ghT[(540 + s) * 18 + r];
            }
            float rr = sigmoid_f(gir + ghr);
            float zz = sigmoid_f(giz + ghz);
            float nn = tanhf(gin + rr * ghn);
            float hn = (1.0f - zz) * nn + zz * sHT[j * 20 + r];
            sHT[j * 20 + r]  = hn;
            sHCT[j * 20 + r] = hn;
        }
        for (int i = tid; i < RT * NL; i += THREADS) {
            int r = i & 15, l = i >> 4;
            sHCT[(NH + l) * 20 + r] = sCur[r * NL + l];
        }
        __syncthreads();

        // ===== Phase D: o1 partials (K-quarters, warp-uniform) =====
        {
            static const int dk0[4] = { 0, 64, 124, 184 };
            static const int dk1[4] = { 64, 124, 184, 244 };
            float* P = giT;   // reuse as [4*180][16] partials
#pragma unroll
            for (int rep = 0; rep < 3; rep++) {
                int R = wid * 3 + rep;          // 0..23
                int q = R / 6, cb = R % 6;
                int col = cb * 32 + lane;
                bool valid = col < NH;
                int cc = valid ? col : NH - 1;
                u64 acc1[8];
                gemm_sing<NH, 20>(sHCT, g_WTo1, cc, dk0[q], dk1[q], acc1);
                if (valid) {
#pragma unroll
                    for (int rp = 0; rp < 8; rp++) {
                        float lo, hi;
                        unpk(acc1[rp], lo, hi);
                        P[(q * NH + col) * 16 + 2 * rp]     = lo;
                        P[(q * NH + col) * 16 + 2 * rp + 1] = hi;
                    }
                }
            }
        }
        __syncthreads();

        // ===== Phase D2: reduce + bias + gelu -> sOT =====
        {
            const float* P = giT;
            for (int i = tid; i < RT * NH; i += THREADS) {
                int r = i & 15, c = i >> 4;
                float v = P[(0 * NH + c) * 16 + r] + P[(1 * NH + c) * 16 + r]
                        + P[(2 * NH + c) * 16 + r] + P[(3 * NH + c) * 16 + r]
                        + b_o1[c];
                sOT[c * 20 + r] = gelu_f(v);
            }
        }
        __syncthreads();

        // ===== Phase E: delta = o @ W_o2^T; cur update; write out; prep sInT =====
        {
            int col = tid & 63;
            int rq  = tid >> 6;     // 4 rows: rq*4 .. rq*4+3
            const float* Wc = g_WTo2 + col;
            const float* A0 = sOT + rq * 4;
            u64 acc0 = 0ull, acc1 = 0ull;
            float w0[4], w1[4], w2[4], w3[4];
            lw4s<NL>(Wc, 0, w0);
            lw4s<NL>(Wc, 4, w1);
            lw4s<NL>(Wc, 8, w2);
            int k = 0;
#pragma unroll 1
            for (; k + 16 <= NH; k += 16) {
                lw4s<NL>(Wc, k + 12, w3);
#pragma unroll
                for (int kk = 0; kk < 4; kk++) {
                    u64 a0, a1; fq(A0 + (k + kk) * 20, a0, a1);
                    u64 wp = dup2(w0[kk]);
                    acc0 = ff2(a0, wp, acc0); acc1 = ff2(a1, wp, acc1);
                }
                lw4s<NL>(Wc, k + 16, w0);
#pragma unroll
                for (int kk = 0; kk < 4; kk++) {
                    u64 a0, a1; fq(A0 + (k + 4 + kk) * 20, a0, a1);
                    u64 wp = dup2(w1[kk]);
                    acc0 = ff2(a0, wp, acc0); acc1 = ff2(a1, wp, acc1);
                }
                lw4s<NL>(Wc, k + 20, w1);
#pragma unroll
                for (int kk = 0; kk < 4; kk++) {
                    u64 a0, a1; fq(A0 + (k + 8 + kk) * 20, a0, a1);
                    u64 wp = dup2(w2[kk]);
                    acc0 = ff2(a0, wp, acc0); acc1 = ff2(a1, wp, acc1);
                }
                lw4s<NL>(Wc, k + 24, w2);
#pragma unroll
                for (int kk = 0; kk < 4; kk++) {
                    u64 a0, a1; fq(A0 + (k + 12 + kk) * 20, a0, a1);
                    u64 wp = dup2(w3[kk]);
                    acc0 = ff2(a0, wp, acc0); acc1 = ff2(a1, wp, acc1);
                }
            }
            if (NH - k >= 4) {
#pragma unroll
                for (int kk = 0; kk < 4; kk++) {
                    u64 a0, a1; fq(A0 + (k + kk) * 20, a0, a1);
                    u64 wp = dup2(w0[kk]);
                    acc0 = ff2(a0, wp, acc0); acc1 = ff2(a1, wp, acc1);
                }
            }
            if (NH - k >= 8) {
#pragma unroll
                for (int kk = 0; kk < 4; kk++) {
                    u64 a0, a1; fq(A0 + (k + 4 + kk) * 20, a0, a1);
                    u64 wp = dup2(w1[kk]);
                    acc0 = ff2(a0, wp, acc0); acc1 = ff2(a1, wp, acc1);
                }
            }
            if (NH - k >= 12) {
#pragma unroll
                for (int kk = 0; kk < 4; kk++) {
                    u64 a0, a1; fq(A0 + (k + 8 + kk) * 20, a0, a1);
                    u64 wp = dup2(w2[kk]);
                    acc0 = ff2(a0, wp, acc0); acc1 = ff2(a1, wp, acc1);
                }
            }
            float v[4];
            unpk(acc0, v[0], v[1]);
            unpk(acc1, v[2], v[3]);
            float bb = b_o2[col];
#pragma unroll
            for (int rr = 0; rr < 4; rr++) {
                int row = rq * 4 + rr;
                float c = sCur[row * NL + col] + v[rr] + bb;
                c = fminf(fmaxf(c, 0.0f), 1.0f);
                sCur[row * NL + col] = c;
                sInT[(NP + col) * 20 + row] = c;
                out[((size_t)(b0 + row) * NT + t) * NL + col] = c;
            }
        }
        if (tid < RT * NP && t + 1 < NT) {
            int r = tid >> 3, p = tid & 7;
            sInT[p * 20 + r] = phys[((size_t)(b0 + r) * NT + t + 1) * NP + p];
        }
        __syncthreads();
    }
}

extern "C" void kernel_launch(void* const* d_in, const int* in_sizes, int n_in,
                              void* d_out, int out_size)
{
    const float* phys    = (const float*)d_in[0];
    const float* latents = (const float*)d_in[1];
    const float* W_in    = (const float*)d_in[2];
    const float* b_in    = (const float*)d_in[3];
    const float* W_hp    = (const float*)d_in[4];
    const float* b_hp    = (const float*)d_in[5];
    const float* W_ih    = (const float*)d_in[6];
    const float* b_ih    = (const float*)d_in[7];
    const float* W_hh    = (const float*)d_in[8];
    const float* b_hh    = (const float*)d_in[9];
    const float* W_o1    = (const float*)d_in[10];
    const float* b_o1    = (const float*)d_in[11];
    const float* W_o2    = (const float*)d_in[12];
    const float* b_o2    = (const float*)d_in[13];
    float* out = (float*)d_out;

    cudaFuncSetAttribute(rnn_kernel,
                         cudaFuncAttributeMaxDynamicSharedMemorySize, SMEM_BYTES);
    rnn_kernel<<<NCTA, THREADS, SMEM_BYTES>>>(phys, latents,
                                              W_in, b_in, W_hp, b_hp,
                                              W_ih, b_ih, W_hh, b_hh,
                                              W_o1, b_o1, W_o2, b_o2, out);
}